// round 2
// baseline (speedup 1.0000x reference)
#include <cuda_runtime.h>
#include <cuda_bf16.h>
#include <math.h>

// ---------------------------------------------------------------------------
// Problem constants (compile-time; shapes are fixed by the dataset)
// ---------------------------------------------------------------------------
#define BB   2            // batch
#define SS   1024         // sequence length
#define NBAR 64           // num bars
#define DD   512          // model dim
#define HH   8            // heads
#define DHH  64           // head dim
#define FF   2048         // ffn dim
#define LL   12           // layers
#define VV   1024         // vocab

#define RR   (BB*SS)      // 2048 regular rows
#define SRR  (BB*NBAR)    // 128 summary rows
#define KTOT (NBAR+SS)    // 1088 keys per batch

// ---------------------------------------------------------------------------
// Device scratch (static; no allocation allowed)
// ---------------------------------------------------------------------------
__device__ float g_x   [RR*DD];
__device__ float g_sum [SRR*DD];
__device__ float g_lnr [RR*DD];
__device__ float g_lns [SRR*DD];
__device__ float g_Qr  [RR*DD];
__device__ float g_Kr  [RR*DD];
__device__ float g_Vr  [RR*DD];
__device__ float g_Or  [RR*DD];
__device__ float g_Qs  [SRR*DD];
__device__ float g_Ks  [SRR*DD];
__device__ float g_Vs  [SRR*DD];
__device__ float g_Os  [SRR*DD];
__device__ float g_h1r [RR*FF];
__device__ float g_h3r [RR*FF];
__device__ float g_h1s [SRR*FF];
__device__ float g_h3s [SRR*FF];

// ---------------------------------------------------------------------------
// Embedding init
// ---------------------------------------------------------------------------
__global__ void embed_kernel(const int* __restrict__ tok,
                             const int* __restrict__ inst,
                             const float* __restrict__ tok_emb,
                             const float* __restrict__ inst_emb,
                             float* __restrict__ x) {
    int row = blockIdx.x;           // 0..RR-1
    int t = tok[row];
    int ii = inst[row]; ii = ii < 0 ? 0 : (ii > 129 ? 129 : ii);
    const float4* te = (const float4*)(tok_emb  + (size_t)t  * DD);
    const float4* ie = (const float4*)(inst_emb + (size_t)ii * DD);
    float4* xo = (float4*)(x + (size_t)row * DD);
    for (int d = threadIdx.x; d < DD/4; d += blockDim.x) {
        float4 a = te[d], b = ie[d];
        xo[d] = make_float4(a.x+b.x, a.y+b.y, a.z+b.z, a.w+b.w);
    }
}

__global__ void sum_init_kernel(const float* __restrict__ bar_emb,
                                float* __restrict__ sum_x) {
    int row = blockIdx.x;           // 0..SRR-1
    int bar = row % NBAR;
    const float4* be = (const float4*)(bar_emb + (size_t)bar * DD);
    float4* so = (float4*)(sum_x + (size_t)row * DD);
    for (int d = threadIdx.x; d < DD/4; d += blockDim.x) so[d] = be[d];
}

// ---------------------------------------------------------------------------
// LayerNorm: one block (256 thr) per row, D=512 (2 elems/thread)
// ---------------------------------------------------------------------------
__global__ void __launch_bounds__(256)
ln_kernel(const float* __restrict__ in,
          const float* __restrict__ g,
          const float* __restrict__ b,
          float* __restrict__ out) {
    int row = blockIdx.x;
    int tid = threadIdx.x;
    const float* xr = in + (size_t)row * DD;
    float v0 = xr[tid], v1 = xr[tid + 256];
    __shared__ float sh[256];
    sh[tid] = v0 + v1; __syncthreads();
    for (int o = 128; o > 0; o >>= 1) { if (tid < o) sh[tid] += sh[tid+o]; __syncthreads(); }
    float mean = sh[0] * (1.0f/DD);
    __syncthreads();
    float d0 = v0 - mean, d1 = v1 - mean;
    sh[tid] = d0*d0 + d1*d1; __syncthreads();
    for (int o = 128; o > 0; o >>= 1) { if (tid < o) sh[tid] += sh[tid+o]; __syncthreads(); }
    float r = rsqrtf(sh[0] * (1.0f/DD) + 1e-5f);
    float* orow = out + (size_t)row * DD;
    orow[tid]       = d0 * r * g[tid]       + b[tid];
    orow[tid + 256] = d1 * r * g[tid + 256] + b[tid + 256];
}

// ---------------------------------------------------------------------------
// RoPE (in-place) over (rows, H, DH) with pos = row % posMod
// ---------------------------------------------------------------------------
__global__ void rope_kernel(float* __restrict__ buf, int rows, int posMod) {
    const float LOGF = 9.210340371976184f / 32.0f;  // log(10000)/32
    int total = rows * HH * (DHH/2);
    for (int idx = blockIdx.x * blockDim.x + threadIdx.x; idx < total;
         idx += gridDim.x * blockDim.x) {
        int row  = idx >> 8;        // 8*32=256 pairs per row
        int rem  = idx & 255;
        int head = rem >> 5;
        int d    = rem & 31;
        int pos  = row % posMod;
        float inv = __expf(-(float)d * LOGF);
        float f = (float)pos * inv;
        float c, s; __sincosf(f, &s, &c);
        float* p = buf + (size_t)row * DD + head * DHH;
        float x1 = p[d], x2 = p[d + 32];
        p[d]      = x1 * c - x2 * s;
        p[d + 32] = x1 * s + x2 * c;
    }
}

// ---------------------------------------------------------------------------
// Fused attention: one block (128 thr) per (query-row, head).
// SUMQ=1 => summary queries (smask), SUMQ=0 => regular queries (umask).
// ---------------------------------------------------------------------------
template<int SUMQ>
__global__ void __launch_bounds__(128)
attn_kernel(const float* __restrict__ Q,
            const float* __restrict__ Ks,
            const float* __restrict__ Kr,
            const float* __restrict__ Vs,
            const float* __restrict__ Vr,
            const int*  __restrict__ chord,
            float* __restrict__ O) {
    const int QN = SUMQ ? NBAR : SS;
    int qrow = blockIdx.x;
    int h    = blockIdx.y;
    int tid  = threadIdx.x;
    int b    = qrow / QN;
    int qi   = qrow % QN;

    __shared__ float shq[DHH];
    __shared__ float sc[KTOT];
    __shared__ float red[128];

    const float* qptr = Q + (size_t)qrow * DD + h * DHH;
    if (tid < DHH) shq[tid] = qptr[tid];
    __syncthreads();

    int cq = SUMQ ? 0 : chord[b * SS + qi];

    const float4* q4 = (const float4*)shq;
    for (int j = tid; j < KTOT; j += 128) {
        bool m;
        const float* kv;
        if (j < NBAR) {
            m  = SUMQ ? (j <= qi) : (j < cq);
            kv = Ks + ((size_t)(b * NBAR + j)) * DD + h * DHH;
        } else {
            int t  = j - NBAR;
            int ck = chord[b * SS + t];
            m  = SUMQ ? (ck == qi) : (ck == cq && qi >= t);
            kv = Kr + ((size_t)(b * SS + t)) * DD + h * DHH;
        }
        float s = -1e9f;
        if (m) {
            const float4* k4 = (const float4*)kv;
            float acc = 0.0f;
            #pragma unroll
            for (int d = 0; d < DHH/4; d++) {
                float4 a = q4[d], kk = k4[d];
                acc += a.x*kk.x + a.y*kk.y + a.z*kk.z + a.w*kk.w;
            }
            s = acc * 0.125f;   // DH^-0.5
        }
        sc[j] = s;
    }
    __syncthreads();

    // max
    float mx = -1e30f;
    for (int j = tid; j < KTOT; j += 128) mx = fmaxf(mx, sc[j]);
    red[tid] = mx; __syncthreads();
    for (int o = 64; o > 0; o >>= 1) { if (tid < o) red[tid] = fmaxf(red[tid], red[tid+o]); __syncthreads(); }
    mx = red[0]; __syncthreads();

    // exp + sum
    float sm = 0.0f;
    for (int j = tid; j < KTOT; j += 128) { float e = expf(sc[j] - mx); sc[j] = e; sm += e; }
    red[tid] = sm; __syncthreads();
    for (int o = 64; o > 0; o >>= 1) { if (tid < o) red[tid] += red[tid+o]; __syncthreads(); }
    float invs = 1.0f / red[0];
    __syncthreads();

    // output: 2 groups x 64 dims
    int dim = tid & 63;
    int grp = tid >> 6;
    float acc = 0.0f;
    for (int j = grp; j < KTOT; j += 2) {
        const float* vv = (j < NBAR)
            ? Vs + ((size_t)(b * NBAR + j)) * DD + h * DHH
            : Vr + ((size_t)(b * SS + (j - NBAR))) * DD + h * DHH;
        acc += sc[j] * vv[dim];
    }
    red[tid] = acc; __syncthreads();
    if (grp == 0)
        O[(size_t)qrow * DD + h * DHH + dim] = (red[tid] + red[tid + 64]) * invs;
}

// ---------------------------------------------------------------------------
// SGEMM: C[M,N] = A[M,K] @ B  (B is K x N, or N x K when TRANSB).
// ACC=1 => C += ...
// 64x64 tile, BK=16, 256 threads, 4x4 per thread.
// Requires M%64==0, N%64==0, K%16==0 (true for all calls here).
// ---------------------------------------------------------------------------
template<int TRANSB, int ACC>
__global__ void __launch_bounds__(256)
sgemm_kernel(const float* __restrict__ A,
             const float* __restrict__ B,
             float* __restrict__ C,
             int M, int N, int K) {
    __shared__ float As[16][64];
    __shared__ float Bs[16][64];
    int tid = threadIdx.x;
    int m0 = blockIdx.y * 64, n0 = blockIdx.x * 64;
    int tx = tid & 15, ty = tid >> 4;

    float acc[4][4] = {};
    int ar  = tid >> 2;     // 0..63
    int ac4 = tid & 3;      // 0..3  (x4 floats)

    for (int k0 = 0; k0 < K; k0 += 16) {
        float4 av = *(const float4*)(A + (size_t)(m0 + ar) * K + k0 + ac4 * 4);
        As[ac4*4+0][ar] = av.x; As[ac4*4+1][ar] = av.y;
        As[ac4*4+2][ar] = av.z; As[ac4*4+3][ar] = av.w;
        if (TRANSB) {
            float4 bv = *(const float4*)(B + (size_t)(n0 + ar) * K + k0 + ac4 * 4);
            Bs[ac4*4+0][ar] = bv.x; Bs[ac4*4+1][ar] = bv.y;
            Bs[ac4*4+2][ar] = bv.z; Bs[ac4*4+3][ar] = bv.w;
        } else {
            int br = tid >> 4, bc4 = tid & 15;
            float4 bv = *(const float4*)(B + (size_t)(k0 + br) * N + n0 + bc4 * 4);
            *(float4*)&Bs[br][bc4*4] = bv;
        }
        __syncthreads();
        #pragma unroll
        for (int kk = 0; kk < 16; kk++) {
            float4 a4 = *(float4*)&As[kk][ty*4];
            float4 b4 = *(float4*)&Bs[kk][tx*4];
            float a[4] = {a4.x, a4.y, a4.z, a4.w};
            float bq[4] = {b4.x, b4.y, b4.z, b4.w};
            #pragma unroll
            for (int i = 0; i < 4; i++)
                #pragma unroll
                for (int j = 0; j < 4; j++)
                    acc[i][j] += a[i] * bq[j];
        }
        __syncthreads();
    }
    #pragma unroll
    for (int i = 0; i < 4; i++) {
        float* cp = C + (size_t)(m0 + ty*4 + i) * N + n0 + tx*4;
        #pragma unroll
        for (int j = 0; j < 4; j++) {
            if (ACC) cp[j] += acc[i][j]; else cp[j] = acc[i][j];
        }
    }
}

// ---------------------------------------------------------------------------
// SwiGLU elementwise: a = silu(a) * b
// ---------------------------------------------------------------------------
__global__ void swiglu_kernel(float* __restrict__ a, const float* __restrict__ b, int n) {
    for (int i = blockIdx.x * blockDim.x + threadIdx.x; i < n;
         i += gridDim.x * blockDim.x) {
        float x = a[i];
        a[i] = x / (1.0f + __expf(-x)) * b[i];
    }
}

// ---------------------------------------------------------------------------
// Host side
// ---------------------------------------------------------------------------
static float* devptr(const void* sym) {
    void* p = nullptr;
    cudaGetSymbolAddress(&p, sym);
    return (float*)p;
}

static void gemm(const float* A, const float* B, float* C,
                 int M, int N, int K, bool transB, bool accum) {
    dim3 g(N / 64, M / 64);
    if (transB) {
        if (accum) sgemm_kernel<1,1><<<g, 256>>>(A, B, C, M, N, K);
        else       sgemm_kernel<1,0><<<g, 256>>>(A, B, C, M, N, K);
    } else {
        if (accum) sgemm_kernel<0,1><<<g, 256>>>(A, B, C, M, N, K);
        else       sgemm_kernel<0,0><<<g, 256>>>(A, B, C, M, N, K);
    }
}

extern "C" void kernel_launch(void* const* d_in, const int* in_sizes, int n_in,
                              void* d_out, int out_size) {
    const int* tok   = (const int*)d_in[0];
    const int* chord = (const int*)d_in[1];
    const int* inst  = (const int*)d_in[2];
    // num_bars may or may not appear as a device input; detect via size.
    int o = (in_sizes[3] == 1) ? 4 : 3;
    const float* tok_emb  = (const float*)d_in[o + 0];
    const float* inst_emb = (const float*)d_in[o + 1];
    const float* bar_emb  = (const float*)d_in[o + 2];
    const float* ln_as_g  = (const float*)d_in[o + 3];
    const float* ln_as_b  = (const float*)d_in[o + 4];
    const float* ln_ar_g  = (const float*)d_in[o + 5];
    const float* ln_ar_b  = (const float*)d_in[o + 6];
    const float* ln_fs_g  = (const float*)d_in[o + 7];
    const float* ln_fs_b  = (const float*)d_in[o + 8];
    const float* ln_fr_g  = (const float*)d_in[o + 9];
    const float* ln_fr_b  = (const float*)d_in[o + 10];
    const float* Wq       = (const float*)d_in[o + 11];
    const float* Wk       = (const float*)d_in[o + 12];
    const float* Wv       = (const float*)d_in[o + 13];
    const float* Wo       = (const float*)d_in[o + 14];
    const float* fs_w1    = (const float*)d_in[o + 15];
    const float* fs_w3    = (const float*)d_in[o + 16];
    const float* fs_w2    = (const float*)d_in[o + 17];
    const float* fr_w1    = (const float*)d_in[o + 18];
    const float* fr_w3    = (const float*)d_in[o + 19];
    const float* fr_w2    = (const float*)d_in[o + 20];
    const float* out_g    = (const float*)d_in[o + 21];
    const float* out_b    = (const float*)d_in[o + 22];
    float* out = (float*)d_out;

    float* x    = devptr(g_x);
    float* sumx = devptr(g_sum);
    float* lnr  = devptr(g_lnr);
    float* lns  = devptr(g_lns);
    float* Qr   = devptr(g_Qr);
    float* Kr   = devptr(g_Kr);
    float* Vr   = devptr(g_Vr);
    float* Or   = devptr(g_Or);
    float* Qs   = devptr(g_Qs);
    float* Ks   = devptr(g_Ks);
    float* Vs   = devptr(g_Vs);
    float* Os   = devptr(g_Os);
    float* h1r  = devptr(g_h1r);
    float* h3r  = devptr(g_h3r);
    float* h1s  = devptr(g_h1s);
    float* h3s  = devptr(g_h3s);

    // Embeddings
    embed_kernel<<<RR, 128>>>(tok, inst, tok_emb, inst_emb, x);
    sum_init_kernel<<<SRR, 128>>>(bar_emb, sumx);

    for (int l = 0; l < LL; l++) {
        const float* wq = Wq + (size_t)l * DD * DD;
        const float* wk = Wk + (size_t)l * DD * DD;
        const float* wv = Wv + (size_t)l * DD * DD;
        const float* wo = Wo + (size_t)l * DD * DD;

        // --- attention ---
        ln_kernel<<<SRR, 256>>>(sumx, ln_as_g + l*DD, ln_as_b + l*DD, lns);
        ln_kernel<<<RR,  256>>>(x,    ln_ar_g + l*DD, ln_ar_b + l*DD, lnr);

        gemm(lns, wq, Qs, SRR, DD, DD, false, false);
        gemm(lnr, wq, Qr, RR,  DD, DD, false, false);
        gemm(lns, wk, Ks, SRR, DD, DD, false, false);
        gemm(lnr, wk, Kr, RR,  DD, DD, false, false);
        gemm(lns, wv, Vs, SRR, DD, DD, false, false);
        gemm(lnr, wv, Vr, RR,  DD, DD, false, false);

        rope_kernel<<<(SRR*256 + 255)/256, 256>>>(Qs, SRR, NBAR);
        rope_kernel<<<(SRR*256 + 255)/256, 256>>>(Ks, SRR, NBAR);
        rope_kernel<<<(RR*256  + 255)/256, 256>>>(Qr, RR,  SS);
        rope_kernel<<<(RR*256  + 255)/256, 256>>>(Kr, RR,  SS);

        attn_kernel<1><<<dim3(SRR, HH), 128>>>(Qs, Ks, Kr, Vs, Vr, chord, Os);
        attn_kernel<0><<<dim3(RR,  HH), 128>>>(Qr, Ks, Kr, Vs, Vr, chord, Or);

        gemm(Os, wo, sumx, SRR, DD, DD, false, true);   // residual add
        gemm(Or, wo, x,    RR,  DD, DD, false, true);

        // --- FFN ---
        ln_kernel<<<SRR, 256>>>(sumx, ln_fs_g + l*DD, ln_fs_b + l*DD, lns);
        ln_kernel<<<RR,  256>>>(x,    ln_fr_g + l*DD, ln_fr_b + l*DD, lnr);

        gemm(lns, fs_w1 + (size_t)l*DD*FF, h1s, SRR, FF, DD, false, false);
        gemm(lns, fs_w3 + (size_t)l*DD*FF, h3s, SRR, FF, DD, false, false);
        gemm(lnr, fr_w1 + (size_t)l*DD*FF, h1r, RR,  FF, DD, false, false);
        gemm(lnr, fr_w3 + (size_t)l*DD*FF, h3r, RR,  FF, DD, false, false);

        swiglu_kernel<<<512, 256>>>(h1s, h3s, SRR*FF);
        swiglu_kernel<<<2048, 256>>>(h1r, h3r, RR*FF);

        gemm(h1s, fs_w2 + (size_t)l*FF*DD, sumx, SRR, DD, FF, false, true);
        gemm(h1r, fr_w2 + (size_t)l*FF*DD, x,    RR,  DD, FF, false, true);
    }

    // Final LN + logits (x @ tok_emb^T)
    ln_kernel<<<RR, 256>>>(x, out_g, out_b, lnr);
    gemm(lnr, tok_emb, out, RR, VV, DD, true, false);
}

// round 4
// speedup vs baseline: 1.8277x; 1.8277x over previous
#include <cuda_runtime.h>
#include <cuda_bf16.h>
#include <math.h>

// ---------------------------------------------------------------------------
// Problem constants
// ---------------------------------------------------------------------------
#define BB   2
#define SS   1024
#define NBAR 64
#define DD   512
#define HH   8
#define DHH  64
#define FF   2048
#define LL   12
#define VV   1024

#define RR   (BB*SS)      // 2048
#define SRR  (BB*NBAR)    // 128
#define KTOT (NBAR+SS)    // 1088

// ---------------------------------------------------------------------------
// Device scratch
// ---------------------------------------------------------------------------
__device__ float g_x   [RR*DD];
__device__ float g_sum [SRR*DD];
__device__ float g_lnr [RR*DD];
__device__ float g_lns [SRR*DD];
__device__ float g_Qr  [RR*DD];
__device__ float g_Kr  [RR*DD];
__device__ float g_Vr  [RR*DD];
__device__ float g_Or  [RR*DD];
__device__ float g_Qs  [SRR*DD];
__device__ float g_Ks  [SRR*DD];
__device__ float g_Vs  [SRR*DD];
__device__ float g_Os  [SRR*DD];
__device__ float g_h1r [RR*FF];
__device__ float g_h3r [RR*FF];
__device__ float g_h1s [SRR*FF];
__device__ float g_h3s [SRR*FF];

// ---------------------------------------------------------------------------
// bf16 split helpers: x = hi + lo with ~16 effective mantissa bits
// ---------------------------------------------------------------------------
__device__ __forceinline__ void split_pack(float x0, float x1,
                                           unsigned& hi, unsigned& lo) {
    __nv_bfloat16 h0 = __float2bfloat16(x0);
    __nv_bfloat16 h1 = __float2bfloat16(x1);
    float r0 = x0 - __bfloat162float(h0);
    float r1 = x1 - __bfloat162float(h1);
    __nv_bfloat16 l0 = __float2bfloat16(r0);
    __nv_bfloat16 l1 = __float2bfloat16(r1);
    hi = ((unsigned)__bfloat16_as_ushort(h1) << 16) | __bfloat16_as_ushort(h0);
    lo = ((unsigned)__bfloat16_as_ushort(l1) << 16) | __bfloat16_as_ushort(l0);
}

__device__ __forceinline__ void mma_bf16(float c[4],
                                         unsigned a0, unsigned a1, unsigned a2, unsigned a3,
                                         unsigned b0, unsigned b1) {
    asm volatile(
        "mma.sync.aligned.m16n8k16.row.col.f32.bf16.bf16.f32 "
        "{%0,%1,%2,%3}, {%4,%5,%6,%7}, {%8,%9}, {%0,%1,%2,%3};"
        : "+f"(c[0]), "+f"(c[1]), "+f"(c[2]), "+f"(c[3])
        : "r"(a0), "r"(a1), "r"(a2), "r"(a3), "r"(b0), "r"(b1));
}

// ---------------------------------------------------------------------------
// bf16x3 tensor-core GEMM: C[M,N] = A[M,K] @ B  (B: KxN, or NxK if TRANSB)
// Error ~2^-16 per operand (drops only lo*lo).
// BM=128, BN=64, BK=16; 256 threads; warp tile 32x32.
// Requires M%128==0, N%64==0, K%16==0.
// smem pair-index stride ≡ 8 mod 32 -> conflict-free fragment loads.
// ---------------------------------------------------------------------------
#define BM 128
#define BN 64
#define BKK 16
#define PAD_M 136
#define PAD_N 72

template<int TRANSB, int ACC>
__global__ void __launch_bounds__(256)
mma_gemm(const float* __restrict__ A, const float* __restrict__ B,
         float* __restrict__ C, int M, int N, int K) {
    __shared__ unsigned AsH[8 * PAD_M];
    __shared__ unsigned AsL[8 * PAD_M];
    __shared__ unsigned BsH[8 * PAD_N];
    __shared__ unsigned BsL[8 * PAD_N];

    int tid  = threadIdx.x;
    int m0 = blockIdx.y * BM, n0 = blockIdx.x * BN;
    int wid = tid >> 5, lane = tid & 31;
    int wm = (wid >> 1) * 32, wn = (wid & 1) * 32;
    int g = lane >> 2, tig = lane & 3;

    float c[2][4][4] = {};

    int am  = tid >> 2;          // A rows handled: am, am+64
    int ak4 = tid & 3;           // float4 index along K -> pairs 2*ak4, 2*ak4+1
    int bp  = tid >> 5;          // B no-trans: pair index 0..7
    int bn2 = (tid & 31) * 2;    // B no-trans: n offset (2 cols)
    int bnr = tid >> 2, bk4 = tid & 3;   // B trans

    for (int k0 = 0; k0 < K; k0 += BKK) {
        #pragma unroll
        for (int i = 0; i < 2; i++) {
            int m = am + i * 64;
            float4 v = *(const float4*)(A + (size_t)(m0 + m) * K + k0 + ak4 * 4);
            unsigned h0, l0, h1, l1;
            split_pack(v.x, v.y, h0, l0);
            split_pack(v.z, v.w, h1, l1);
            AsH[(ak4*2+0)*PAD_M + m] = h0; AsL[(ak4*2+0)*PAD_M + m] = l0;
            AsH[(ak4*2+1)*PAD_M + m] = h1; AsL[(ak4*2+1)*PAD_M + m] = l1;
        }
        if (TRANSB) {
            float4 v = *(const float4*)(B + (size_t)(n0 + bnr) * K + k0 + bk4 * 4);
            unsigned h0, l0, h1, l1;
            split_pack(v.x, v.y, h0, l0);
            split_pack(v.z, v.w, h1, l1);
            BsH[(bk4*2+0)*PAD_N + bnr] = h0; BsL[(bk4*2+0)*PAD_N + bnr] = l0;
            BsH[(bk4*2+1)*PAD_N + bnr] = h1; BsL[(bk4*2+1)*PAD_N + bnr] = l1;
        } else {
            // pair = rows k0+2bp, k0+2bp+1; two n columns each
            float2 r0 = *(const float2*)(B + (size_t)(k0 + 2*bp    ) * N + n0 + bn2);
            float2 r1 = *(const float2*)(B + (size_t)(k0 + 2*bp + 1) * N + n0 + bn2);
            unsigned h0, l0, h1, l1;
            split_pack(r0.x, r1.x, h0, l0);   // n = bn2
            split_pack(r0.y, r1.y, h1, l1);   // n = bn2+1
            BsH[bp*PAD_N + bn2    ] = h0; BsL[bp*PAD_N + bn2    ] = l0;
            BsH[bp*PAD_N + bn2 + 1] = h1; BsL[bp*PAD_N + bn2 + 1] = l1;
        }
        __syncthreads();

        unsigned ah[2][4], al[2][4], bh[4][2], bl[4][2];
        #pragma unroll
        for (int mt = 0; mt < 2; mt++) {
            int mr = wm + mt * 16 + g;
            ah[mt][0] = AsH[(tig  )*PAD_M + mr];
            ah[mt][1] = AsH[(tig  )*PAD_M + mr + 8];
            ah[mt][2] = AsH[(tig+4)*PAD_M + mr];
            ah[mt][3] = AsH[(tig+4)*PAD_M + mr + 8];
            al[mt][0] = AsL[(tig  )*PAD_M + mr];
            al[mt][1] = AsL[(tig  )*PAD_M + mr + 8];
            al[mt][2] = AsL[(tig+4)*PAD_M + mr];
            al[mt][3] = AsL[(tig+4)*PAD_M + mr + 8];
        }
        #pragma unroll
        for (int nt = 0; nt < 4; nt++) {
            int nc = wn + nt * 8 + g;
            bh[nt][0] = BsH[(tig  )*PAD_N + nc];
            bh[nt][1] = BsH[(tig+4)*PAD_N + nc];
            bl[nt][0] = BsL[(tig  )*PAD_N + nc];
            bl[nt][1] = BsL[(tig+4)*PAD_N + nc];
        }
        #pragma unroll
        for (int mt = 0; mt < 2; mt++)
            #pragma unroll
            for (int nt = 0; nt < 4; nt++) {
                mma_bf16(c[mt][nt], ah[mt][0], ah[mt][1], ah[mt][2], ah[mt][3],
                         bh[nt][0], bh[nt][1]);
                mma_bf16(c[mt][nt], ah[mt][0], ah[mt][1], ah[mt][2], ah[mt][3],
                         bl[nt][0], bl[nt][1]);
                mma_bf16(c[mt][nt], al[mt][0], al[mt][1], al[mt][2], al[mt][3],
                         bh[nt][0], bh[nt][1]);
            }
        __syncthreads();
    }

    #pragma unroll
    for (int mt = 0; mt < 2; mt++) {
        #pragma unroll
        for (int r = 0; r < 2; r++) {
            int row = m0 + wm + mt * 16 + g + r * 8;
            #pragma unroll
            for (int nt = 0; nt < 4; nt++) {
                float* cp = C + (size_t)row * N + n0 + wn + nt * 8 + 2 * tig;
                float v0 = c[mt][nt][r*2+0], v1 = c[mt][nt][r*2+1];
                if (ACC) { cp[0] += v0; cp[1] += v1; }
                else     { cp[0]  = v0; cp[1]  = v1; }
            }
        }
    }
}

// ---------------------------------------------------------------------------
// Embedding init
// ---------------------------------------------------------------------------
__global__ void embed_kernel(const int* __restrict__ tok,
                             const int* __restrict__ inst,
                             const float* __restrict__ tok_emb,
                             const float* __restrict__ inst_emb,
                             float* __restrict__ x) {
    int row = blockIdx.x;
    int t = tok[row];
    int ii = inst[row]; ii = ii < 0 ? 0 : (ii > 129 ? 129 : ii);
    const float4* te = (const float4*)(tok_emb  + (size_t)t  * DD);
    const float4* ie = (const float4*)(inst_emb + (size_t)ii * DD);
    float4* xo = (float4*)(x + (size_t)row * DD);
    for (int d = threadIdx.x; d < DD/4; d += blockDim.x) {
        float4 a = te[d], b = ie[d];
        xo[d] = make_float4(a.x+b.x, a.y+b.y, a.z+b.z, a.w+b.w);
    }
}

__global__ void sum_init_kernel(const float* __restrict__ bar_emb,
                                float* __restrict__ sum_x) {
    int row = blockIdx.x;
    int bar = row % NBAR;
    const float4* be = (const float4*)(bar_emb + (size_t)bar * DD);
    float4* so = (float4*)(sum_x + (size_t)row * DD);
    for (int d = threadIdx.x; d < DD/4; d += blockDim.x) so[d] = be[d];
}

// ---------------------------------------------------------------------------
// LayerNorm
// ---------------------------------------------------------------------------
__global__ void __launch_bounds__(256)
ln_kernel(const float* __restrict__ in,
          const float* __restrict__ g,
          const float* __restrict__ b,
          float* __restrict__ out) {
    int row = blockIdx.x;
    int tid = threadIdx.x;
    const float* xr = in + (size_t)row * DD;
    float v0 = xr[tid], v1 = xr[tid + 256];
    __shared__ float sh[256];
    sh[tid] = v0 + v1; __syncthreads();
    for (int o = 128; o > 0; o >>= 1) { if (tid < o) sh[tid] += sh[tid+o]; __syncthreads(); }
    float mean = sh[0] * (1.0f/DD);
    __syncthreads();
    float d0 = v0 - mean, d1 = v1 - mean;
    sh[tid] = d0*d0 + d1*d1; __syncthreads();
    for (int o = 128; o > 0; o >>= 1) { if (tid < o) sh[tid] += sh[tid+o]; __syncthreads(); }
    float r = rsqrtf(sh[0] * (1.0f/DD) + 1e-5f);
    float* orow = out + (size_t)row * DD;
    orow[tid]       = d0 * r * g[tid]       + b[tid];
    orow[tid + 256] = d1 * r * g[tid + 256] + b[tid + 256];
}

// ---------------------------------------------------------------------------
// RoPE (in-place)
// ---------------------------------------------------------------------------
__global__ void rope_kernel(float* __restrict__ buf, int rows, int posMod) {
    const float LOGF = 9.210340371976184f / 32.0f;
    int total = rows * HH * (DHH/2);
    for (int idx = blockIdx.x * blockDim.x + threadIdx.x; idx < total;
         idx += gridDim.x * blockDim.x) {
        int row  = idx >> 8;
        int rem  = idx & 255;
        int head = rem >> 5;
        int d    = rem & 31;
        int pos  = row % posMod;
        float inv = __expf(-(float)d * LOGF);
        float f = (float)pos * inv;
        float c, s; __sincosf(f, &s, &c);
        float* p = buf + (size_t)row * DD + head * DHH;
        float x1 = p[d], x2 = p[d + 32];
        p[d]      = x1 * c - x2 * s;
        p[d + 32] = x1 * s + x2 * c;
    }
}

// ---------------------------------------------------------------------------
// Range-based sparse attention (chord_ids sorted -> 2 contiguous key ranges)
// ---------------------------------------------------------------------------
template<int SUMQ>
__global__ void __launch_bounds__(64)
attn_kernel(const float* __restrict__ Q,
            const float* __restrict__ Ks,
            const float* __restrict__ Kr,
            const float* __restrict__ Vs,
            const float* __restrict__ Vr,
            const int*  __restrict__ chord,
            float* __restrict__ O) {
    const int QN = SUMQ ? NBAR : SS;
    int qrow = blockIdx.x;
    int h    = blockIdx.y;
    int tid  = threadIdx.x;
    int b    = qrow / QN;
    int qi   = qrow % QN;
    const int* ch = chord + b * SS;

    __shared__ float shq[DHH];
    __shared__ float sc[KTOT];
    __shared__ float red[64];

    if (tid < DHH) shq[tid] = Q[(size_t)qrow * DD + h * DHH + tid];

    int target = SUMQ ? qi : ch[qi];
    int lo = 0, hi = SS;
    while (lo < hi) { int mid = (lo + hi) >> 1; if (ch[mid] < target) lo = mid + 1; else hi = mid; }
    int tstart = lo;
    int n1, n2;
    if (SUMQ) {
        int lo2 = tstart, hi2 = SS;
        while (lo2 < hi2) { int mid = (lo2 + hi2) >> 1; if (ch[mid] < target + 1) lo2 = mid + 1; else hi2 = mid; }
        n1 = qi + 1;
        n2 = lo2 - tstart;
    } else {
        n1 = target;
        n2 = qi - tstart + 1;
    }
    int n = n1 + n2;
    __syncthreads();

    const float4* q4 = (const float4*)shq;
    for (int j = tid; j < n; j += 64) {
        const float* kv = (j < n1)
            ? Ks + ((size_t)(b * NBAR + j)) * DD + h * DHH
            : Kr + ((size_t)(b * SS + tstart + (j - n1))) * DD + h * DHH;
        const float4* k4 = (const float4*)kv;
        float acc = 0.0f;
        #pragma unroll
        for (int d = 0; d < DHH/4; d++) {
            float4 a = q4[d], kk = k4[d];
            acc += a.x*kk.x + a.y*kk.y + a.z*kk.z + a.w*kk.w;
        }
        sc[j] = acc * 0.125f;
    }
    __syncthreads();

    float mx = -1e30f;
    for (int j = tid; j < n; j += 64) mx = fmaxf(mx, sc[j]);
    red[tid] = mx; __syncthreads();
    for (int o = 32; o > 0; o >>= 1) { if (tid < o) red[tid] = fmaxf(red[tid], red[tid+o]); __syncthreads(); }
    mx = red[0]; __syncthreads();

    float sm = 0.0f;
    for (int j = tid; j < n; j += 64) { float e = __expf(sc[j] - mx); sc[j] = e; sm += e; }
    red[tid] = sm; __syncthreads();
    for (int o = 32; o > 0; o >>= 1) { if (tid < o) red[tid] += red[tid+o]; __syncthreads(); }
    float invs = 1.0f / red[0];
    __syncthreads();

    float acc = 0.0f;
    for (int j = 0; j < n; j++) {
        const float* vv = (j < n1)
            ? Vs + ((size_t)(b * NBAR + j)) * DD + h * DHH
            : Vr + ((size_t)(b * SS + tstart + (j - n1))) * DD + h * DHH;
        acc += sc[j] * vv[tid];
    }
    O[(size_t)qrow * DD + h * DHH + tid] = acc * invs;
}

// ---------------------------------------------------------------------------
// SwiGLU elementwise: a = silu(a) * b
// ---------------------------------------------------------------------------
__global__ void swiglu_kernel(float* __restrict__ a, const float* __restrict__ b, int n) {
    for (int i = blockIdx.x * blockDim.x + threadIdx.x; i < n;
         i += gridDim.x * blockDim.x) {
        float x = a[i];
        a[i] = x / (1.0f + __expf(-x)) * b[i];
    }
}

// ---------------------------------------------------------------------------
// Host side
// ---------------------------------------------------------------------------
static float* devptr(const void* sym) {
    void* p = nullptr;
    cudaGetSymbolAddress(&p, sym);
    return (float*)p;
}

static void gemm(const float* A, const float* B, float* C,
                 int M, int N, int K, bool transB, bool accum) {
    dim3 g(N / BN, M / BM);
    if (transB) {
        if (accum) mma_gemm<1,1><<<g, 256>>>(A, B, C, M, N, K);
        else       mma_gemm<1,0><<<g, 256>>>(A, B, C, M, N, K);
    } else {
        if (accum) mma_gemm<0,1><<<g, 256>>>(A, B, C, M, N, K);
        else       mma_gemm<0,0><<<g, 256>>>(A, B, C, M, N, K);
    }
}

extern "C" void kernel_launch(void* const* d_in, const int* in_sizes, int n_in,
                              void* d_out, int out_size) {
    const int* tok   = (const int*)d_in[0];
    const int* chord = (const int*)d_in[1];
    const int* inst  = (const int*)d_in[2];
    int o = (in_sizes[3] == 1) ? 4 : 3;
    const float* tok_emb  = (const float*)d_in[o + 0];
    const float* inst_emb = (const float*)d_in[o + 1];
    const float* bar_emb  = (const float*)d_in[o + 2];
    const float* ln_as_g  = (const float*)d_in[o + 3];
    const float* ln_as_b  = (const float*)d_in[o + 4];
    const float* ln_ar_g  = (const float*)d_in[o + 5];
    const float* ln_ar_b  = (const float*)d_in[o + 6];
    const float* ln_fs_g  = (const float*)d_in[o + 7];
    const float* ln_fs_b  = (const float*)d_in[o + 8];
    const float* ln_fr_g  = (const float*)d_in[o + 9];
    const float* ln_fr_b  = (const float*)d_in[o + 10];
    const float* Wq       = (const float*)d_in[o + 11];
    const float* Wk       = (const float*)d_in[o + 12];
    const float* Wv       = (const float*)d_in[o + 13];
    const float* Wo       = (const float*)d_in[o + 14];
    const float* fs_w1    = (const float*)d_in[o + 15];
    const float* fs_w3    = (const float*)d_in[o + 16];
    const float* fs_w2    = (const float*)d_in[o + 17];
    const float* fr_w1    = (const float*)d_in[o + 18];
    const float* fr_w3    = (const float*)d_in[o + 19];
    const float* fr_w2    = (const float*)d_in[o + 20];
    const float* out_g    = (const float*)d_in[o + 21];
    const float* out_b    = (const float*)d_in[o + 22];
    float* out = (float*)d_out;

    float* x    = devptr(g_x);
    float* sumx = devptr(g_sum);
    float* lnr  = devptr(g_lnr);
    float* lns  = devptr(g_lns);
    float* Qr   = devptr(g_Qr);
    float* Kr   = devptr(g_Kr);
    float* Vr   = devptr(g_Vr);
    float* Or   = devptr(g_Or);
    float* Qs   = devptr(g_Qs);
    float* Ks   = devptr(g_Ks);
    float* Vs   = devptr(g_Vs);
    float* Os   = devptr(g_Os);
    float* h1r  = devptr(g_h1r);
    float* h3r  = devptr(g_h3r);
    float* h1s  = devptr(g_h1s);
    float* h3s  = devptr(g_h3s);

    embed_kernel<<<RR, 128>>>(tok, inst, tok_emb, inst_emb, x);
    sum_init_kernel<<<SRR, 128>>>(bar_emb, sumx);

    for (int l = 0; l < LL; l++) {
        const float* wq = Wq + (size_t)l * DD * DD;
        const float* wk = Wk + (size_t)l * DD * DD;
        const float* wv = Wv + (size_t)l * DD * DD;
        const float* wo = Wo + (size_t)l * DD * DD;

        ln_kernel<<<SRR, 256>>>(sumx, ln_as_g + l*DD, ln_as_b + l*DD, lns);
        ln_kernel<<<RR,  256>>>(x,    ln_ar_g + l*DD, ln_ar_b + l*DD, lnr);

        gemm(lns, wq, Qs, SRR, DD, DD, false, false);
        gemm(lnr, wq, Qr, RR,  DD, DD, false, false);
        gemm(lns, wk, Ks, SRR, DD, DD, false, false);
        gemm(lnr, wk, Kr, RR,  DD, DD, false, false);
        gemm(lns, wv, Vs, SRR, DD, DD, false, false);
        gemm(lnr, wv, Vr, RR,  DD, DD, false, false);

        rope_kernel<<<(SRR*256 + 255)/256, 256>>>(Qs, SRR, NBAR);
        rope_kernel<<<(SRR*256 + 255)/256, 256>>>(Ks, SRR, NBAR);
        rope_kernel<<<(RR*256  + 255)/256, 256>>>(Qr, RR,  SS);
        rope_kernel<<<(RR*256  + 255)/256, 256>>>(Kr, RR,  SS);

        attn_kernel<1><<<dim3(SRR, HH), 64>>>(Qs, Ks, Kr, Vs, Vr, chord, Os);
        attn_kernel<0><<<dim3(RR,  HH), 64>>>(Qr, Ks, Kr, Vs, Vr, chord, Or);

        gemm(Os, wo, sumx, SRR, DD, DD, false, true);
        gemm(Or, wo, x,    RR,  DD, DD, false, true);

        ln_kernel<<<SRR, 256>>>(sumx, ln_fs_g + l*DD, ln_fs_b + l*DD, lns);
        ln_kernel<<<RR,  256>>>(x,    ln_fr_g + l*DD, ln_fr_b + l*DD, lnr);

        gemm(lns, fs_w1 + (size_t)l*DD*FF, h1s, SRR, FF, DD, false, false);
        gemm(lns, fs_w3 + (size_t)l*DD*FF, h3s, SRR, FF, DD, false, false);
        gemm(lnr, fr_w1 + (size_t)l*DD*FF, h1r, RR,  FF, DD, false, false);
        gemm(lnr, fr_w3 + (size_t)l*DD*FF, h3r, RR,  FF, DD, false, false);

        swiglu_kernel<<<512, 256>>>(h1s, h3s, SRR*FF);
        swiglu_kernel<<<2048, 256>>>(h1r, h3r, RR*FF);

        gemm(h1s, fs_w2 + (size_t)l*FF*DD, sumx, SRR, DD, FF, false, true);
        gemm(h1r, fr_w2 + (size_t)l*FF*DD, x,    RR,  DD, FF, false, true);
    }

    ln_kernel<<<RR, 256>>>(x, out_g, out_b, lnr);
    gemm(lnr, tok_emb, out, RR, VV, DD, true, false);
}